// round 9
// baseline (speedup 1.0000x reference)
#include <cuda_runtime.h>
#include <cuda_bf16.h>
#include <math.h>

#define V_   50000
#define E_   256
#define H_   256
#define G4_  1024
#define HD_  512
#define T_   50
#define B_   128
#define S_   512

typedef unsigned long long u64;
typedef unsigned int u32;

// ---------------------------------------------------------------------------
// Device scratch
// ---------------------------------------------------------------------------
__device__ __nv_bfloat16 g_embb[(size_t)V_ * E_];
__device__ __nv_bfloat16 g_wihb[(size_t)2 * G4_ * E_];
__device__ __nv_bfloat16 g_woutb[(size_t)64 * HD_];        // padded [64][512]
// G layout: [d][s][slice(32)][gate(4)][b(128)][u(8)] bf16
__device__ __nv_bfloat16 g_Gb[(size_t)2 * S_ * B_ * G4_];
__device__ __nv_bfloat16 g_hb[(size_t)2 * S_ * B_ * H_];   // [d][s][b][k]
__device__ __align__(16) float g_emis[(size_t)S_ * B_ * T_];
__device__ float g_res[B_];
__device__ u32 g_flags[4][32];   // flag-array barrier, monotonic across launches

// ---------------------------------------------------------------------------
// Helpers
// ---------------------------------------------------------------------------
__device__ __forceinline__ u64 pk2(float lo, float hi) {
    u64 r; asm("mov.b64 %0, {%1, %2};" : "=l"(r) : "f"(lo), "f"(hi)); return r;
}
__device__ __forceinline__ u64 f2ma(u64 a, u64 b, u64 c) {
    u64 d; asm("fma.rn.f32x2 %0, %1, %2, %3;" : "=l"(d) : "l"(a), "l"(b), "l"(c)); return d;
}
__device__ __forceinline__ u64 f2add(u64 a, u64 b) {
    u64 d; asm("add.rn.f32x2 %0, %1, %2;" : "=l"(d) : "l"(a), "l"(b)); return d;
}
__device__ __forceinline__ float2 upk(u64 v) {
    float2 f; asm("mov.b64 {%0, %1}, %2;" : "=f"(f.x), "=f"(f.y) : "l"(v)); return f;
}
__device__ __forceinline__ u32 smem_u32(const void* p) { return (u32)__cvta_generic_to_shared(p); }
__device__ __forceinline__ void cp16(void* smem, const void* g) {
    asm volatile("cp.async.cg.shared.global [%0], [%1], 16;" :: "r"(smem_u32(smem)), "l"(g));
}
#define CP_COMMIT() asm volatile("cp.async.commit_group;")
#define CP_WAIT0()  asm volatile("cp.async.wait_group 0;")
#define CP_WAIT1()  asm volatile("cp.async.wait_group 1;")

__device__ __forceinline__ u32 bfpack(float lo, float hi) {
    u32 r; asm("cvt.rn.bf16x2.f32 %0, %1, %2;" : "=r"(r) : "f"(hi), "f"(lo)); return r;
}
__device__ __forceinline__ float tanhx(float x) {
    float r; asm("tanh.approx.f32 %0, %1;" : "=f"(r) : "f"(x)); return r;
}
__device__ __forceinline__ float sigx(float x) { return 0.5f * tanhx(0.5f * x) + 0.5f; }

__device__ __forceinline__ void ldsm4(u32& r0, u32& r1, u32& r2, u32& r3, u32 addr) {
    asm volatile("ldmatrix.sync.aligned.m8n8.x4.shared.b16 {%0,%1,%2,%3}, [%4];"
                 : "=r"(r0), "=r"(r1), "=r"(r2), "=r"(r3) : "r"(addr));
}
__device__ __forceinline__ void ldsm2(u32& r0, u32& r1, u32 addr) {
    asm volatile("ldmatrix.sync.aligned.m8n8.x2.shared.b16 {%0,%1}, [%2];"
                 : "=r"(r0), "=r"(r1) : "r"(addr));
}
__device__ __forceinline__ void hmma(float* d, u32 a0, u32 a1, u32 a2, u32 a3, u32 b0, u32 b1) {
    asm volatile(
        "mma.sync.aligned.m16n8k16.row.col.f32.bf16.bf16.f32 "
        "{%0,%1,%2,%3}, {%4,%5,%6,%7}, {%8,%9}, {%0,%1,%2,%3};"
        : "+f"(d[0]), "+f"(d[1]), "+f"(d[2]), "+f"(d[3])
        : "r"(a0), "r"(a1), "r"(a2), "r"(a3), "r"(b0), "r"(b1));
}

__device__ __forceinline__ u32 ld_acq(const u32* p) {
    u32 v; asm volatile("ld.acquire.gpu.u32 %0, [%1];" : "=r"(v) : "l"(p) : "memory"); return v;
}
__device__ __forceinline__ void st_rel(u32* p, u32 v) {
    asm volatile("st.release.gpu.u32 [%0], %1;" :: "l"(p), "r"(v) : "memory");
}

// ---------------------------------------------------------------------------
// K0: convert emb + W_ih + W_out(padded to 64 rows) to bf16
// ---------------------------------------------------------------------------
#define EMB2  ((V_ * E_) / 2)
#define WIH2  ((G4_ * E_) / 2)
#define WOUT2 ((64 * HD_) / 2)
__global__ void __launch_bounds__(256) k_convert(
    const float* __restrict__ emb, const float* __restrict__ wf,
    const float* __restrict__ wb,  const float* __restrict__ wo)
{
    int i = blockIdx.x * 256 + threadIdx.x;
    if (i >= EMB2 + 2 * WIH2 + WOUT2) return;
    float2 v; __nv_bfloat162* dst;
    if (i < EMB2)                 { v = ((const float2*)emb)[i];              dst = (__nv_bfloat162*)g_embb + i; }
    else if (i < EMB2 + WIH2)     { v = ((const float2*)wf)[i - EMB2];        dst = (__nv_bfloat162*)g_wihb + (i - EMB2); }
    else if (i < EMB2 + 2 * WIH2) { v = ((const float2*)wb)[i - EMB2 - WIH2]; dst = (__nv_bfloat162*)g_wihb + (i - EMB2); }
    else {
        int j = i - EMB2 - 2 * WIH2;
        int tag = (j * 2) >> 9, k = (j * 2) & 511;
        v.x = (tag < T_) ? wo[(size_t)tag * HD_ + k] : 0.f;
        v.y = (tag < T_) ? wo[(size_t)tag * HD_ + k + 1] : 0.f;
        dst = (__nv_bfloat162*)g_woutb + j;
    }
    *dst = __floats2bfloat162_rn(v.x, v.y);
}

// ---------------------------------------------------------------------------
// K1: input projection via mma.sync bf16. grid (8 jt, 2 d, 256 sp), block 256.
// Two timesteps per CTA; G stored coalesced in [slice][gate][b][u] layout.
// ---------------------------------------------------------------------------
__global__ void __launch_bounds__(256) k_input(
    const int* __restrict__ sent,
    const float* __restrict__ bih_f, const float* __restrict__ bhh_f,
    const float* __restrict__ bih_b, const float* __restrict__ bhh_b)
{
    extern __shared__ __align__(16) char smraw[];
    char* sm = smraw + ((1024 - (smem_u32(smraw) & 1023)) & 1023);
    char* smB  = sm;
    char* smA0 = sm + 65536;
    char* smA1 = sm + 131072;
    int*  toks0 = (int*)(sm + 196608);
    int*  toks1 = (int*)(sm + 197120);
    float* bsm  = (float*)(sm + 197632);

    const int jt = blockIdx.x, d = blockIdx.y, sp = blockIdx.z;
    const int s0 = 2 * sp, s1 = 2 * sp + 1;
    const int j0 = jt * 128;
    const int g  = jt >> 1;            // gate index
    const int nb = (jt & 1) * 128;     // unit base within gate
    const int t = threadIdx.x;
    const int l = t & 31, w = t >> 5;
    const int wm = w & 3, wn = w >> 2;

    if (t < 128) {
        toks0[t] = sent[t * S_ + s0];
        toks1[t] = sent[t * S_ + s1];
        const float* bi = d ? bih_b : bih_f;
        const float* bh = d ? bhh_b : bhh_f;
        bsm[t] = bi[j0 + t] + bh[j0 + t];
    }
    __syncthreads();

    for (int i = t; i < 4096; i += 256) {
        int row = i >> 5, c = i & 31;
        cp16(smB + row * 512 + ((c ^ (row & 7)) * 16),
             (const char*)(g_wihb + ((size_t)d * G4_ + j0 + row) * E_) + c * 16);
    }
    CP_COMMIT();
    for (int i = t; i < 4096; i += 256) {
        int row = i >> 5, c = i & 31;
        cp16(smA0 + row * 512 + ((c ^ (row & 7)) * 16),
             (const char*)(g_embb + (size_t)toks0[row] * E_) + c * 16);
    }
    CP_COMMIT();
    for (int i = t; i < 4096; i += 256) {
        int row = i >> 5, c = i & 31;
        cp16(smA1 + row * 512 + ((c ^ (row & 7)) * 16),
             (const char*)(g_embb + (size_t)toks1[row] * E_) + c * 16);
    }
    CP_COMMIT();

    const u32 smB_b = smem_u32(smB);

    auto tile = [&](u32 smA_b, int s) {
        float acc[2][8][4];
#pragma unroll
        for (int m = 0; m < 2; m++)
#pragma unroll
            for (int n = 0; n < 8; n++)
#pragma unroll
                for (int q = 0; q < 4; q++) acc[m][n][q] = 0.f;

#pragma unroll 4
        for (int kk = 0; kk < 16; kk++) {
            u32 a[2][4];
#pragma unroll
            for (int m = 0; m < 2; m++) {
                int row = wm * 32 + m * 16 + (l & 15);
                int c = kk * 2 + (l >> 4);
                ldsm4(a[m][0], a[m][1], a[m][2], a[m][3],
                      smA_b + row * 512 + ((c ^ (row & 7)) * 16));
            }
#pragma unroll
            for (int nt = 0; nt < 8; nt++) {
                int row = wn * 64 + nt * 8 + (l & 7);
                int c = kk * 2 + ((l >> 3) & 1);
                u32 b0, b1;
                ldsm2(b0, b1, smB_b + row * 512 + ((c ^ (row & 7)) * 16));
#pragma unroll
                for (int m = 0; m < 2; m++)
                    hmma(acc[m][nt], a[m][0], a[m][1], a[m][2], a[m][3], b0, b1);
            }
        }

        __nv_bfloat16* Gss = g_Gb + (size_t)(d * S_ + s) * (size_t)(B_ * G4_);
#pragma unroll
        for (int m = 0; m < 2; m++)
#pragma unroll
        for (int nt = 0; nt < 8; nt++) {
            int b  = wm * 32 + m * 16 + (l >> 2);
            int jl = wn * 64 + nt * 8 + 2 * (l & 3);
            int n  = nb + jl;
            int slice = n >> 3, u = n & 7;
            float bb0 = bsm[jl], bb1 = bsm[jl + 1];
            __nv_bfloat16* p = Gss + (size_t)slice * 4096 + g * 1024 + (size_t)b * 8 + u;
            *(u32*)p        = bfpack(acc[m][nt][0] + bb0, acc[m][nt][1] + bb1);
            *(u32*)(p + 64) = bfpack(acc[m][nt][2] + bb0, acc[m][nt][3] + bb1);  // b+8
        }
    };

    CP_WAIT1();
    __syncthreads();
    tile(smem_u32(smA0), s0);
    CP_WAIT0();
    __syncthreads();
    tile(smem_u32(smA1), s1);
}

// ---------------------------------------------------------------------------
// K2: persistent bidirectional LSTM (R7 structure). grid 128, block 128.
// CTA = (d = cta>>6, bhalf = (cta>>5)&1, slice = cta&31). M=64, N=32, K=256.
// 4 independent groups of 32 CTAs; flag-array barrier (no same-address
// atomics: 32 distinct release-stores + 32-lane parallel acquire polls).
// ---------------------------------------------------------------------------
__global__ void __launch_bounds__(128, 1) k_lstm(
    const float* __restrict__ whh_f, const float* __restrict__ whh_b)
{
    extern __shared__ __align__(16) char smraw[];
    char* sm = smraw + ((1024 - (smem_u32(smraw) & 1023)) & 1023);
    char* smA = sm;                  // 32KB h tile [64 b][512B]
    char* smW = sm + 32768;          // 16KB W_hh slice [32][256] bf16

    const int cta   = blockIdx.x;
    const int d     = cta >> 6;
    const int bh    = (cta >> 5) & 1;
    const int slice = cta & 31;
    const int n0    = slice * 8;
    const int grp   = cta >> 5;      // 0..3
    const int t     = threadIdx.x;
    const int l = t & 31, w = t >> 5;
    const float* __restrict__ Wh = d ? whh_b : whh_f;

    // flag-array barrier base: all slots in a group are equal at launch start
    // (monotonic; each launch adds 511 to every slot).
    const u32 base = ld_acq(&g_flags[grp][slice]);

    for (int i = t; i < 8192; i += 128) {
        int row = i >> 8, k = i & 255;
        int j = ((row >> 3) * 256) + n0 + (row & 7);
        int c = k >> 3;
        *(__nv_bfloat16*)(smW + row * 512 + ((c ^ (row & 7)) * 16) + (k & 7) * 2) =
            __float2bfloat16(Wh[(size_t)j * H_ + k]);
    }
    {
        uint4 z = make_uint4(0, 0, 0, 0);
        for (int i = t; i < 2048; i += 128) ((uint4*)smA)[i] = z;
    }
    __syncthreads();

    const u32 smA_b = smem_u32(smA), smW_b = smem_u32(smW);
    const int qbl = w * 16 + (l >> 2);       // local b (and +8)
    const int u0  = 2 * (l & 3);

    float cst[4];
#pragma unroll
    for (int u = 0; u < 4; u++) cst[u] = 0.f;

    __nv_bfloat16* Hd = g_hb + (size_t)d * S_ * B_ * H_;

    u32 gq[8], gqn[8];
    {
        const int ss0 = d ? (S_ - 1) : 0;
        const __nv_bfloat16* Gp = g_Gb + (size_t)(d * S_ + ss0) * (size_t)(B_ * G4_)
                                 + (size_t)slice * 4096;
#pragma unroll
        for (int i = 0; i < 2; i++) {
            int b = bh * 64 + qbl + 8 * i;
#pragma unroll
            for (int gg = 0; gg < 4; gg++)
                gqn[i * 4 + gg] = *(const u32*)(Gp + gg * 1024 + (size_t)b * 8 + u0);
        }
    }

    for (int step = 0; step < S_; step++) {
        const int s = d ? (S_ - 1 - step) : step;

#pragma unroll
        for (int j = 0; j < 8; j++) gq[j] = gqn[j];
        if (step + 1 < S_) {
            const int sn = d ? (S_ - 2 - step) : (step + 1);
            const __nv_bfloat16* Gp = g_Gb + (size_t)(d * S_ + sn) * (size_t)(B_ * G4_)
                                     + (size_t)slice * 4096;
#pragma unroll
            for (int i = 0; i < 2; i++) {
                int b = bh * 64 + qbl + 8 * i;
#pragma unroll
                for (int gg = 0; gg < 4; gg++)
                    gqn[i * 4 + gg] = *(const u32*)(Gp + gg * 1024 + (size_t)b * 8 + u0);
            }
        }

        if (step > 0) {
            const char* hsrc = (const char*)(Hd + ((size_t)(d ? s + 1 : s - 1) * B_ + bh * 64) * H_);
            for (int i = t; i < 1024; i += 128) {
                int row = i >> 4, c = i & 15;
                cp16(smA + row * 512 + ((c ^ (row & 7)) * 16), hsrc + row * 512 + c * 16);
            }
            CP_COMMIT();
            for (int i = t; i < 1024; i += 128) {
                int row = i >> 4, c = (i & 15) + 16;
                cp16(smA + row * 512 + ((c ^ (row & 7)) * 16), hsrc + row * 512 + c * 16);
            }
            CP_COMMIT();
        }

        float acc[4][4];
#pragma unroll
        for (int g = 0; g < 4; g++)
#pragma unroll
            for (int q = 0; q < 4; q++) acc[g][q] = 0.f;

        CP_WAIT1();
        __syncthreads();
#pragma unroll
        for (int kk = 0; kk < 8; kk++) {
            u32 a0r, a1r, a2r, a3r;
            {
                int row = w * 16 + (l & 15);
                int c = kk * 2 + (l >> 4);
                ldsm4(a0r, a1r, a2r, a3r, smA_b + row * 512 + ((c ^ (row & 7)) * 16));
            }
#pragma unroll
            for (int g = 0; g < 4; g++) {
                int row = g * 8 + (l & 7);
                int c = kk * 2 + ((l >> 3) & 1);
                u32 b0, b1;
                ldsm2(b0, b1, smW_b + row * 512 + ((c ^ (row & 7)) * 16));
                hmma(acc[g], a0r, a1r, a2r, a3r, b0, b1);
            }
        }
        CP_WAIT0();
        __syncthreads();
#pragma unroll
        for (int kk = 8; kk < 16; kk++) {
            u32 a0r, a1r, a2r, a3r;
            {
                int row = w * 16 + (l & 15);
                int c = kk * 2 + (l >> 4);
                ldsm4(a0r, a1r, a2r, a3r, smA_b + row * 512 + ((c ^ (row & 7)) * 16));
            }
#pragma unroll
            for (int g = 0; g < 4; g++) {
                int row = g * 8 + (l & 7);
                int c = kk * 2 + ((l >> 3) & 1);
                u32 b0, b1;
                ldsm2(b0, b1, smW_b + row * 512 + ((c ^ (row & 7)) * 16));
                hmma(acc[g], a0r, a1r, a2r, a3r, b0, b1);
            }
        }

        // combine + store h
#pragma unroll
        for (int i = 0; i < 2; i++) {
            const int bl = qbl + 8 * i;
            const int e = 2 * i;
            float2 gi = __bfloat1622float2(*(const __nv_bfloat162*)&gq[i * 4 + 0]);
            float2 gf = __bfloat1622float2(*(const __nv_bfloat162*)&gq[i * 4 + 1]);
            float2 gg = __bfloat1622float2(*(const __nv_bfloat162*)&gq[i * 4 + 2]);
            float2 go = __bfloat1622float2(*(const __nv_bfloat162*)&gq[i * 4 + 3]);
            const int ci = 2 * i;
            float c0 = sigx(acc[1][e] + gf.x) * cst[ci]
                     + sigx(acc[0][e] + gi.x) * tanhx(acc[2][e] + gg.x);
            cst[ci] = c0;
            float h0 = sigx(acc[3][e] + go.x) * tanhx(c0);
            float c1 = sigx(acc[1][e + 1] + gf.y) * cst[ci + 1]
                     + sigx(acc[0][e + 1] + gi.y) * tanhx(acc[2][e + 1] + gg.y);
            cst[ci + 1] = c1;
            float h1 = sigx(acc[3][e + 1] + go.y) * tanhx(c1);
            *(u32*)(Hd + ((size_t)s * B_ + bh * 64 + bl) * H_ + n0 + u0) = bfpack(h0, h1);
        }

        // flag-array grid barrier (group of 32 CTAs)
        if (step != S_ - 1) {
            __syncthreads();
            const u32 tgt = base + (u32)(step + 1);
            if (t == 0) st_rel(&g_flags[grp][slice], tgt);
            if (t < 32) {
                while ((int)(ld_acq(&g_flags[grp][t]) - tgt) < 0) { __nanosleep(20); }
            }
            __syncthreads();
        }
    }
}

// ---------------------------------------------------------------------------
// K3: emissions via mma.sync. grid 512 (s), block 128.
// ---------------------------------------------------------------------------
__global__ void __launch_bounds__(128) k_emis(const float* __restrict__ bo)
{
    extern __shared__ __align__(16) char smraw[];
    char* sm = smraw + ((1024 - (smem_u32(smraw) & 1023)) & 1023);
    char* smW  = sm;
    char* smA0 = sm + 65536;
    char* smA1 = sm + 131072;
    float* bsm = (float*)(sm + 196608);

    const int s = blockIdx.x;
    const int t = threadIdx.x;
    const int l = t & 31, w = t >> 5;

    if (t < 64) bsm[t] = (t < T_) ? bo[t] : 0.f;

    for (int i = t; i < 4096; i += 128) {
        int row = i >> 6, c = i & 63;
        cp16(smW + row * 1024 + ((c ^ (row & 7)) * 16),
             (const char*)g_woutb + row * 1024 + c * 16);
    }
    CP_COMMIT();
    for (int i = t; i < 4096; i += 128) {
        int row = i >> 5, c = i & 31;
        cp16(smA0 + row * 512 + ((c ^ (row & 7)) * 16),
             (const char*)(g_hb + ((size_t)s * B_ + row) * H_) + c * 16);
    }
    CP_COMMIT();
    for (int i = t; i < 4096; i += 128) {
        int row = i >> 5, c = i & 31;
        cp16(smA1 + row * 512 + ((c ^ (row & 7)) * 16),
             (const char*)(g_hb + (size_t)S_ * B_ * H_ + ((size_t)s * B_ + row) * H_) + c * 16);
    }
    CP_COMMIT();

    const u32 smW_b = smem_u32(smW);

    float acc[2][8][4];
#pragma unroll
    for (int m = 0; m < 2; m++)
#pragma unroll
        for (int n = 0; n < 8; n++)
#pragma unroll
            for (int q = 0; q < 4; q++) acc[m][n][q] = 0.f;

    auto stage = [&](u32 smA_b, int wc0) {
#pragma unroll 4
        for (int kk = 0; kk < 16; kk++) {
            u32 a[2][4];
#pragma unroll
            for (int m = 0; m < 2; m++) {
                int row = w * 32 + m * 16 + (l & 15);
                int c = kk * 2 + (l >> 4);
                ldsm4(a[m][0], a[m][1], a[m][2], a[m][3],
                      smA_b + row * 512 + ((c ^ (row & 7)) * 16));
            }
#pragma unroll
            for (int nt = 0; nt < 8; nt++) {
                int row = nt * 8 + (l & 7);
                int c = wc0 + kk * 2 + ((l >> 3) & 1);
                u32 b0, b1;
                ldsm2(b0, b1, smW_b + row * 1024 + ((c ^ (row & 7)) * 16));
#pragma unroll
                for (int m = 0; m < 2; m++)
                    hmma(acc[m][nt], a[m][0], a[m][1], a[m][2], a[m][3], b0, b1);
            }
        }
    };

    CP_WAIT1();
    __syncthreads();
    stage(smem_u32(smA0), 0);
    CP_WAIT0();
    __syncthreads();
    stage(smem_u32(smA1), 32);

#pragma unroll
    for (int m = 0; m < 2; m++)
#pragma unroll
    for (int nt = 0; nt < 8; nt++) {
        int r  = w * 32 + m * 16 + (l >> 2);
        int jl = nt * 8 + 2 * (l & 3);
        if (jl < T_) {
            float b0 = bsm[jl], b1 = bsm[jl + 1];
            *(float2*)(g_emis + ((size_t)s * B_ + r) * T_ + jl)     = make_float2(acc[m][nt][0] + b0, acc[m][nt][1] + b1);
            *(float2*)(g_emis + ((size_t)s * B_ + r + 8) * T_ + jl) = make_float2(acc[m][nt][2] + b0, acc[m][nt][3] + b1);
        }
    }
}

// ---------------------------------------------------------------------------
// K4: CRF — one warp per batch element, 128 CTAs.
// ---------------------------------------------------------------------------
__global__ void __launch_bounds__(32) k_crf(
    const float* __restrict__ trans, const float* __restrict__ start_t,
    const float* __restrict__ end_t, const int* __restrict__ tags)
{
    __shared__ __align__(16) u64 Esp[T_ * 32];
    __shared__ float pw[64];

    const int b = blockIdx.x;
    const int l = threadIdx.x;

    for (int i = l; i < T_ * 32; i += 32) {
        int tt = i >> 5, c = i & 31;
        float e0 = expf(trans[tt * T_ + c]);
        float e1 = (c + 32 < T_) ? expf(trans[tt * T_ + c + 32]) : 0.f;
        Esp[i] = pk2(e0, e1);
    }
    __syncwarp();

    const bool v1 = (l + 32 < T_);
    float a0 = start_t[l] + g_emis[(size_t)b * T_ + l];
    float a1 = v1 ? (start_t[l + 32] + g_emis[(size_t)b * T_ + l + 32]) : -1e30f;

    float e0n = g_emis[((size_t)B_ + b) * T_ + l];
    float e1n = v1 ? g_emis[((size_t)B_ + b) * T_ + l + 32] : 0.f;

    for (int s = 1; s < S_; s++) {
        float e0 = e0n, e1 = e1n;
        if (s + 1 < S_) {
            const float* es = g_emis + ((size_t)(s + 1) * B_ + b) * T_;
            e0n = es[l];
            e1n = v1 ? es[l + 32] : 0.f;
        }

        float m = __shfl_sync(0xffffffffu, a0, 0);
        pw[l]      = __expf(a0 - m);
        pw[l + 32] = v1 ? __expf(a1 - m) : 0.f;
        __syncwarp();

        u64 q0 = 0ull, q1 = 0ull, q2 = 0ull, q3 = 0ull;
#pragma unroll
        for (int tt = 0; tt < 48; tt += 4) {
            q0 = f2ma(pk2(pw[tt],     pw[tt]),     Esp[(tt)     * 32 + l], q0);
            q1 = f2ma(pk2(pw[tt + 1], pw[tt + 1]), Esp[(tt + 1) * 32 + l], q1);
            q2 = f2ma(pk2(pw[tt + 2], pw[tt + 2]), Esp[(tt + 2) * 32 + l], q2);
            q3 = f2ma(pk2(pw[tt + 3], pw[tt + 3]), Esp[(tt + 3) * 32 + l], q3);
        }
        q0 = f2ma(pk2(pw[48], pw[48]), Esp[48 * 32 + l], q0);
        q1 = f2ma(pk2(pw[49], pw[49]), Esp[49 * 32 + l], q1);
        float2 qf = upk(f2add(f2add(q0, q1), f2add(q2, q3)));
        a0 = m + __logf(qf.x) + e0;
        a1 = v1 ? (m + __logf(qf.y) + e1) : -1e30f;
        __syncwarp();
    }

    float vv0 = a0 + end_t[l];
    float vv1 = v1 ? (a1 + end_t[l + 32]) : -1e30f;
    float m = fmaxf(vv0, vv1);
#pragma unroll
    for (int o = 16; o; o >>= 1) m = fmaxf(m, __shfl_xor_sync(0xffffffffu, m, o));
    float e = __expf(vv0 - m) + (v1 ? __expf(vv1 - m) : 0.f);
#pragma unroll
    for (int o = 16; o; o >>= 1) e += __shfl_xor_sync(0xffffffffu, e, o);
    float logZ = m + __logf(e);

    float acc = 0.f;
    for (int s = 1 + l; s < S_; s += 32) {
        int tp = tags[b * S_ + s - 1];
        int tc = tags[b * S_ + s];
        acc += trans[tp * T_ + tc] + g_emis[((size_t)s * B_ + b) * T_ + tc];
    }
#pragma unroll
    for (int o = 16; o; o >>= 1) acc += __shfl_xor_sync(0xffffffffu, acc, o);

    if (l == 0) {
        int t0 = tags[b * S_];
        int tl = tags[b * S_ + S_ - 1];
        g_res[b] = logZ - (start_t[t0] + g_emis[(size_t)b * T_ + t0] + acc + end_t[tl]);
    }
}

// ---------------------------------------------------------------------------
// K5: final mean
// ---------------------------------------------------------------------------
__global__ void k_final(float* __restrict__ out)
{
    __shared__ float red[4];
    int t = threadIdx.x;
    float v = g_res[t];
#pragma unroll
    for (int o = 16; o; o >>= 1) v += __shfl_xor_sync(0xffffffffu, v, o);
    if ((t & 31) == 0) red[t >> 5] = v;
    __syncthreads();
    if (t == 0) out[0] = (red[0] + red[1] + red[2] + red[3]) * (1.f / (float)B_);
}

// ---------------------------------------------------------------------------
// Launch
// ---------------------------------------------------------------------------
extern "C" void kernel_launch(void* const* d_in, const int* in_sizes, int n_in,
                              void* d_out, int out_size)
{
    const int*   sent  = (const int*)  d_in[0];
    const int*   tags  = (const int*)  d_in[1];
    const float* emb   = (const float*)d_in[3];
    const float* wih_f = (const float*)d_in[4];
    const float* whh_f = (const float*)d_in[5];
    const float* bih_f = (const float*)d_in[6];
    const float* bhh_f = (const float*)d_in[7];
    const float* wih_b = (const float*)d_in[8];
    const float* whh_b = (const float*)d_in[9];
    const float* bih_b = (const float*)d_in[10];
    const float* bhh_b = (const float*)d_in[11];
    const float* Wout  = (const float*)d_in[12];
    const float* bout  = (const float*)d_in[13];
    const float* strt  = (const float*)d_in[14];
    const float* endt  = (const float*)d_in[15];
    const float* trans = (const float*)d_in[16];
    float* out = (float*)d_out;

    const int input_smem = 199168;
    const int lstm_smem  = 50176;
    const int emis_smem  = 197888;
    cudaFuncSetAttribute(k_input, cudaFuncAttributeMaxDynamicSharedMemorySize, input_smem);
    cudaFuncSetAttribute(k_lstm,  cudaFuncAttributeMaxDynamicSharedMemorySize, lstm_smem);
    cudaFuncSetAttribute(k_emis,  cudaFuncAttributeMaxDynamicSharedMemorySize, emis_smem);

    int nconv = (EMB2 + 2 * WIH2 + WOUT2 + 255) / 256;
    k_convert<<<nconv, 256>>>(emb, wih_f, wih_b, Wout);
    k_input<<<dim3(8, 2, 256), 256, input_smem>>>(sent, bih_f, bhh_f, bih_b, bhh_b);
    k_lstm<<<128, 128, lstm_smem>>>(whh_f, whh_b);
    k_emis<<<512, 128, emis_smem>>>(bout);
    k_crf<<<128, 32>>>(trans, strt, endt, tags);
    k_final<<<1, 128>>>(out);
}

// round 10
// speedup vs baseline: 2.3456x; 2.3456x over previous
#include <cuda_runtime.h>
#include <cuda_bf16.h>
#include <math.h>

#define V_   50000
#define E_   256
#define H_   256
#define G4_  1024
#define HD_  512
#define T_   50
#define B_   128
#define S_   512

typedef unsigned long long u64;
typedef unsigned int u32;

// ---------------------------------------------------------------------------
// Device scratch
// ---------------------------------------------------------------------------
__device__ __nv_bfloat16 g_embb[(size_t)V_ * E_];
__device__ __nv_bfloat16 g_wihb[(size_t)2 * G4_ * E_];
__device__ __nv_bfloat16 g_woutb[(size_t)64 * HD_];        // padded [64][512]
__device__ __nv_bfloat16 g_Gb[(size_t)2 * S_ * B_ * G4_];  // [d][s][b][j]
__device__ __nv_bfloat16 g_hb[(size_t)2 * S_ * B_ * H_];   // [d][s][b][k]
__device__ __align__(16) float g_emis[(size_t)S_ * B_ * T_];
__device__ float g_res[B_];
__device__ u32 g_barcnt[4];     // monotonic arrival counters; zeroed by k_convert

// ---------------------------------------------------------------------------
// Helpers
// ---------------------------------------------------------------------------
__device__ __forceinline__ u64 pk2(float lo, float hi) {
    u64 r; asm("mov.b64 %0, {%1, %2};" : "=l"(r) : "f"(lo), "f"(hi)); return r;
}
__device__ __forceinline__ u64 f2ma(u64 a, u64 b, u64 c) {
    u64 d; asm("fma.rn.f32x2 %0, %1, %2, %3;" : "=l"(d) : "l"(a), "l"(b), "l"(c)); return d;
}
__device__ __forceinline__ u64 f2add(u64 a, u64 b) {
    u64 d; asm("add.rn.f32x2 %0, %1, %2;" : "=l"(d) : "l"(a), "l"(b)); return d;
}
__device__ __forceinline__ float2 upk(u64 v) {
    float2 f; asm("mov.b64 {%0, %1}, %2;" : "=f"(f.x), "=f"(f.y) : "l"(v)); return f;
}
__device__ __forceinline__ u32 smem_u32(const void* p) { return (u32)__cvta_generic_to_shared(p); }
__device__ __forceinline__ void cp16(void* smem, const void* g) {
    asm volatile("cp.async.cg.shared.global [%0], [%1], 16;" :: "r"(smem_u32(smem)), "l"(g));
}
#define CP_COMMIT() asm volatile("cp.async.commit_group;")
#define CP_WAIT0()  asm volatile("cp.async.wait_group 0;")
#define CP_WAIT1()  asm volatile("cp.async.wait_group 1;")

__device__ __forceinline__ u32 bfpack(float lo, float hi) {
    u32 r; asm("cvt.rn.bf16x2.f32 %0, %1, %2;" : "=r"(r) : "f"(hi), "f"(lo)); return r;
}
__device__ __forceinline__ float tanhx(float x) {
    float r; asm("tanh.approx.f32 %0, %1;" : "=f"(r) : "f"(x)); return r;
}
__device__ __forceinline__ float sigx(float x) { return 0.5f * tanhx(0.5f * x) + 0.5f; }

__device__ __forceinline__ void ldsm4(u32& r0, u32& r1, u32& r2, u32& r3, u32 addr) {
    asm volatile("ldmatrix.sync.aligned.m8n8.x4.shared.b16 {%0,%1,%2,%3}, [%4];"
                 : "=r"(r0), "=r"(r1), "=r"(r2), "=r"(r3) : "r"(addr));
}
__device__ __forceinline__ void ldsm2(u32& r0, u32& r1, u32 addr) {
    asm volatile("ldmatrix.sync.aligned.m8n8.x2.shared.b16 {%0,%1}, [%2];"
                 : "=r"(r0), "=r"(r1) : "r"(addr));
}
__device__ __forceinline__ void hmma(float* d, u32 a0, u32 a1, u32 a2, u32 a3, u32 b0, u32 b1) {
    asm volatile(
        "mma.sync.aligned.m16n8k16.row.col.f32.bf16.bf16.f32 "
        "{%0,%1,%2,%3}, {%4,%5,%6,%7}, {%8,%9}, {%0,%1,%2,%3};"
        : "+f"(d[0]), "+f"(d[1]), "+f"(d[2]), "+f"(d[3])
        : "r"(a0), "r"(a1), "r"(a2), "r"(a3), "r"(b0), "r"(b1));
}

__device__ __forceinline__ u32 ld_acq(const u32* p) {
    u32 v; asm volatile("ld.acquire.gpu.u32 %0, [%1];" : "=r"(v) : "l"(p) : "memory"); return v;
}
__device__ __forceinline__ u32 atom_add_rel(u32* p, u32 v) {
    u32 o; asm volatile("atom.release.gpu.add.u32 %0, [%1], %2;" : "=r"(o) : "l"(p), "r"(v) : "memory"); return o;
}

// ---------------------------------------------------------------------------
// K0: convert emb + W_ih + W_out(padded to 64 rows) to bf16; reset barriers
// ---------------------------------------------------------------------------
#define EMB2  ((V_ * E_) / 2)
#define WIH2  ((G4_ * E_) / 2)
#define WOUT2 ((64 * HD_) / 2)
__global__ void __launch_bounds__(256) k_convert(
    const float* __restrict__ emb, const float* __restrict__ wf,
    const float* __restrict__ wb,  const float* __restrict__ wo)
{
    if (blockIdx.x == 0 && threadIdx.x < 4) g_barcnt[threadIdx.x] = 0;  // ordered before k_lstm (same stream)
    int i = blockIdx.x * 256 + threadIdx.x;
    if (i >= EMB2 + 2 * WIH2 + WOUT2) return;
    float2 v; __nv_bfloat162* dst;
    if (i < EMB2)                 { v = ((const float2*)emb)[i];              dst = (__nv_bfloat162*)g_embb + i; }
    else if (i < EMB2 + WIH2)     { v = ((const float2*)wf)[i - EMB2];        dst = (__nv_bfloat162*)g_wihb + (i - EMB2); }
    else if (i < EMB2 + 2 * WIH2) { v = ((const float2*)wb)[i - EMB2 - WIH2]; dst = (__nv_bfloat162*)g_wihb + (i - EMB2); }
    else {
        int j = i - EMB2 - 2 * WIH2;
        int tag = (j * 2) >> 9, k = (j * 2) & 511;
        v.x = (tag < T_) ? wo[(size_t)tag * HD_ + k] : 0.f;
        v.y = (tag < T_) ? wo[(size_t)tag * HD_ + k + 1] : 0.f;
        dst = (__nv_bfloat162*)g_woutb + j;
    }
    *dst = __floats2bfloat162_rn(v.x, v.y);
}

// ---------------------------------------------------------------------------
// K1: input projection via mma.sync bf16. grid (8 jt, 2 d, 256 sp), block 256.
// Two timesteps per CTA reusing the W tile. (R7 layout: G[d][s][b][j])
// ---------------------------------------------------------------------------
__global__ void __launch_bounds__(256) k_input(
    const int* __restrict__ sent,
    const float* __restrict__ bih_f, const float* __restrict__ bhh_f,
    const float* __restrict__ bih_b, const float* __restrict__ bhh_b)
{
    extern __shared__ __align__(16) char smraw[];
    char* sm = smraw + ((1024 - (smem_u32(smraw) & 1023)) & 1023);
    char* smB  = sm;
    char* smA0 = sm + 65536;
    char* smA1 = sm + 131072;
    int*  toks0 = (int*)(sm + 196608);
    int*  toks1 = (int*)(sm + 197120);
    float* bsm  = (float*)(sm + 197632);

    const int jt = blockIdx.x, d = blockIdx.y, sp = blockIdx.z;
    const int s0 = 2 * sp, s1 = 2 * sp + 1;
    const int j0 = jt * 128;
    const int t = threadIdx.x;
    const int l = t & 31, w = t >> 5;
    const int wm = w & 3, wn = w >> 2;

    if (t < 128) {
        toks0[t] = sent[t * S_ + s0];
        toks1[t] = sent[t * S_ + s1];
        const float* bi = d ? bih_b : bih_f;
        const float* bh = d ? bhh_b : bhh_f;
        bsm[t] = bi[j0 + t] + bh[j0 + t];
    }
    __syncthreads();

    for (int i = t; i < 4096; i += 256) {
        int row = i >> 5, c = i & 31;
        cp16(smB + row * 512 + ((c ^ (row & 7)) * 16),
             (const char*)(g_wihb + ((size_t)d * G4_ + j0 + row) * E_) + c * 16);
    }
    CP_COMMIT();
    for (int i = t; i < 4096; i += 256) {
        int row = i >> 5, c = i & 31;
        cp16(smA0 + row * 512 + ((c ^ (row & 7)) * 16),
             (const char*)(g_embb + (size_t)toks0[row] * E_) + c * 16);
    }
    CP_COMMIT();
    for (int i = t; i < 4096; i += 256) {
        int row = i >> 5, c = i & 31;
        cp16(smA1 + row * 512 + ((c ^ (row & 7)) * 16),
             (const char*)(g_embb + (size_t)toks1[row] * E_) + c * 16);
    }
    CP_COMMIT();

    const u32 smB_b = smem_u32(smB);

    auto tile = [&](u32 smA_b, int s) {
        float acc[2][8][4];
#pragma unroll
        for (int m = 0; m < 2; m++)
#pragma unroll
            for (int n = 0; n < 8; n++)
#pragma unroll
                for (int q = 0; q < 4; q++) acc[m][n][q] = 0.f;

#pragma unroll 4
        for (int kk = 0; kk < 16; kk++) {
            u32 a[2][4];
#pragma unroll
            for (int m = 0; m < 2; m++) {
                int row = wm * 32 + m * 16 + (l & 15);
                int c = kk * 2 + (l >> 4);
                ldsm4(a[m][0], a[m][1], a[m][2], a[m][3],
                      smA_b + row * 512 + ((c ^ (row & 7)) * 16));
            }
#pragma unroll
            for (int nt = 0; nt < 8; nt++) {
                int row = wn * 64 + nt * 8 + (l & 7);
                int c = kk * 2 + ((l >> 3) & 1);
                u32 b0, b1;
                ldsm2(b0, b1, smB_b + row * 512 + ((c ^ (row & 7)) * 16));
#pragma unroll
                for (int m = 0; m < 2; m++)
                    hmma(acc[m][nt], a[m][0], a[m][1], a[m][2], a[m][3], b0, b1);
            }
        }

        __nv_bfloat16* Gbase = g_Gb + ((size_t)(d * S_ + s) * B_) * G4_;
#pragma unroll
        for (int m = 0; m < 2; m++)
#pragma unroll
        for (int nt = 0; nt < 8; nt++) {
            int r  = wm * 32 + m * 16 + (l >> 2);
            int jl = wn * 64 + nt * 8 + 2 * (l & 3);
            float b0 = bsm[jl], b1 = bsm[jl + 1];
            *(u32*)(Gbase + (size_t)r * G4_ + j0 + jl)       = bfpack(acc[m][nt][0] + b0, acc[m][nt][1] + b1);
            *(u32*)(Gbase + (size_t)(r + 8) * G4_ + j0 + jl) = bfpack(acc[m][nt][2] + b0, acc[m][nt][3] + b1);
        }
    };

    CP_WAIT1();
    __syncthreads();
    tile(smem_u32(smA0), s0);
    CP_WAIT0();
    __syncthreads();
    tile(smem_u32(smA1), s1);
}

// ---------------------------------------------------------------------------
// K2: persistent bidirectional LSTM (R7 structure). grid 128, block 128.
// CTA = (d = cta>>6, bhalf = (cta>>5)&1, slice = cta&31). M=64, N=32, K=256.
// 4 independent groups of 32 CTAs; MONOTONIC-COUNTER barrier:
// arrive = atom.release.add(cnt,1); wait = poll cnt >= 32*(step+1).
// No leader, no reset, no phase: one L2 hop after the last arrival.
// ---------------------------------------------------------------------------
__global__ void __launch_bounds__(128, 1) k_lstm(
    const float* __restrict__ whh_f, const float* __restrict__ whh_b)
{
    extern __shared__ __align__(16) char smraw[];
    char* sm = smraw + ((1024 - (smem_u32(smraw) & 1023)) & 1023);
    char* smA = sm;                  // 32KB h tile [64 b][512B]
    char* smW = sm + 32768;          // 16KB W_hh slice [32][256] bf16

    const int cta   = blockIdx.x;
    const int d     = cta >> 6;
    const int bh    = (cta >> 5) & 1;
    const int slice = cta & 31;
    const int n0    = slice * 8;
    const int grp   = cta >> 5;      // 0..3
    const int t     = threadIdx.x;
    const int l = t & 31, w = t >> 5;
    const float* __restrict__ Wh = d ? whh_b : whh_f;

    for (int i = t; i < 8192; i += 128) {
        int row = i >> 8, k = i & 255;
        int j = ((row >> 3) * 256) + n0 + (row & 7);
        int c = k >> 3;
        *(__nv_bfloat16*)(smW + row * 512 + ((c ^ (row & 7)) * 16) + (k & 7) * 2) =
            __float2bfloat16(Wh[(size_t)j * H_ + k]);
    }
    {
        uint4 z = make_uint4(0, 0, 0, 0);
        for (int i = t; i < 2048; i += 128) ((uint4*)smA)[i] = z;
    }
    __syncthreads();

    const u32 smA_b = smem_u32(smA), smW_b = smem_u32(smW);
    const int qbl = w * 16 + (l >> 2);       // local b (and +8)
    const int u0  = 2 * (l & 3);

    float cst[4];
#pragma unroll
    for (int u = 0; u < 4; u++) cst[u] = 0.f;

    const __nv_bfloat16* Gd = g_Gb + (size_t)d * S_ * B_ * G4_;
    __nv_bfloat16*       Hd = g_hb + (size_t)d * S_ * B_ * H_;

    u32 gq[8], gqn[8];
    {
        const __nv_bfloat16* Gp = Gd + (size_t)(d ? S_ - 1 : 0) * B_ * G4_;
#pragma unroll
        for (int i = 0; i < 2; i++) {
            int b = bh * 64 + qbl + 8 * i;
#pragma unroll
            for (int gg = 0; gg < 4; gg++)
                gqn[i * 4 + gg] = *(const u32*)(Gp + (size_t)b * G4_ + gg * 256 + n0 + u0);
        }
    }

    for (int step = 0; step < S_; step++) {
        const int s = d ? (S_ - 1 - step) : step;

#pragma unroll
        for (int j = 0; j < 8; j++) gq[j] = gqn[j];
        if (step + 1 < S_) {
            const int sn = d ? (S_ - 2 - step) : (step + 1);
            const __nv_bfloat16* Gp = Gd + (size_t)sn * B_ * G4_;
#pragma unroll
            for (int i = 0; i < 2; i++) {
                int b = bh * 64 + qbl + 8 * i;
#pragma unroll
                for (int gg = 0; gg < 4; gg++)
                    gqn[i * 4 + gg] = *(const u32*)(Gp + (size_t)b * G4_ + gg * 256 + n0 + u0);
            }
        }

        if (step > 0) {
            const char* hsrc = (const char*)(Hd + ((size_t)(d ? s + 1 : s - 1) * B_ + bh * 64) * H_);
            for (int i = t; i < 1024; i += 128) {
                int row = i >> 4, c = i & 15;
                cp16(smA + row * 512 + ((c ^ (row & 7)) * 16), hsrc + row * 512 + c * 16);
            }
            CP_COMMIT();
            for (int i = t; i < 1024; i += 128) {
                int row = i >> 4, c = (i & 15) + 16;
                cp16(smA + row * 512 + ((c ^ (row & 7)) * 16), hsrc + row * 512 + c * 16);
            }
            CP_COMMIT();
        }

        float acc[4][4];
#pragma unroll
        for (int g = 0; g < 4; g++)
#pragma unroll
            for (int q = 0; q < 4; q++) acc[g][q] = 0.f;

        CP_WAIT1();
        __syncthreads();
#pragma unroll
        for (int kk = 0; kk < 8; kk++) {
            u32 a0r, a1r, a2r, a3r;
            {
                int row = w * 16 + (l & 15);
                int c = kk * 2 + (l >> 4);
                ldsm4(a0r, a1r, a2r, a3r, smA_b + row * 512 + ((c ^ (row & 7)) * 16));
            }
#pragma unroll
            for (int g = 0; g < 4; g++) {
                int row = g * 8 + (l & 7);
                int c = kk * 2 + ((l >> 3) & 1);
                u32 b0, b1;
                ldsm2(b0, b1, smW_b + row * 512 + ((c ^ (row & 7)) * 16));
                hmma(acc[g], a0r, a1r, a2r, a3r, b0, b1);
            }
        }
        CP_WAIT0();
        __syncthreads();
#pragma unroll
        for (int kk = 8; kk < 16; kk++) {
            u32 a0r, a1r, a2r, a3r;
            {
                int row = w * 16 + (l & 15);
                int c = kk * 2 + (l >> 4);
                ldsm4(a0r, a1r, a2r, a3r, smA_b + row * 512 + ((c ^ (row & 7)) * 16));
            }
#pragma unroll
            for (int g = 0; g < 4; g++) {
                int row = g * 8 + (l & 7);
                int c = kk * 2 + ((l >> 3) & 1);
                u32 b0, b1;
                ldsm2(b0, b1, smW_b + row * 512 + ((c ^ (row & 7)) * 16));
                hmma(acc[g], a0r, a1r, a2r, a3r, b0, b1);
            }
        }

        // combine + store h
#pragma unroll
        for (int i = 0; i < 2; i++) {
            const int bl = qbl + 8 * i;
            const int e = 2 * i;
            float2 gi = __bfloat1622float2(*(const __nv_bfloat162*)&gq[i * 4 + 0]);
            float2 gf = __bfloat1622float2(*(const __nv_bfloat162*)&gq[i * 4 + 1]);
            float2 gg = __bfloat1622float2(*(const __nv_bfloat162*)&gq[i * 4 + 2]);
            float2 go = __bfloat1622float2(*(const __nv_bfloat162*)&gq[i * 4 + 3]);
            const int ci = 2 * i;
            float c0 = sigx(acc[1][e] + gf.x) * cst[ci]
                     + sigx(acc[0][e] + gi.x) * tanhx(acc[2][e] + gg.x);
            cst[ci] = c0;
            float h0 = sigx(acc[3][e] + go.x) * tanhx(c0);
            float c1 = sigx(acc[1][e + 1] + gf.y) * cst[ci + 1]
                     + sigx(acc[0][e + 1] + gi.y) * tanhx(acc[2][e + 1] + gg.y);
            cst[ci + 1] = c1;
            float h1 = sigx(acc[3][e + 1] + go.y) * tanhx(c1);
            *(u32*)(Hd + ((size_t)s * B_ + bh * 64 + bl) * H_ + n0 + u0) = bfpack(h0, h1);
        }

        // monotonic-counter grid barrier (group of 32 CTAs)
        if (step != S_ - 1) {
            __syncthreads();
            if (t == 0) {
                atom_add_rel(&g_barcnt[grp], 1);
                const u32 tgt = (u32)(32 * (step + 1));
                while ((int)(ld_acq(&g_barcnt[grp]) - tgt) < 0) { __nanosleep(20); }
            }
            __syncthreads();
        }
    }
}

// ---------------------------------------------------------------------------
// K3: emissions via mma.sync. grid 512 (s), block 128.
// ---------------------------------------------------------------------------
__global__ void __launch_bounds__(128) k_emis(const float* __restrict__ bo)
{
    extern __shared__ __align__(16) char smraw[];
    char* sm = smraw + ((1024 - (smem_u32(smraw) & 1023)) & 1023);
    char* smW  = sm;
    char* smA0 = sm + 65536;
    char* smA1 = sm + 131072;
    float* bsm = (float*)(sm + 196608);

    const int s = blockIdx.x;
    const int t = threadIdx.x;
    const int l = t & 31, w = t >> 5;

    if (t < 64) bsm[t] = (t < T_) ? bo[t] : 0.f;

    for (int i = t; i < 4096; i += 128) {
        int row = i >> 6, c = i & 63;
        cp16(smW + row * 1024 + ((c ^ (row & 7)) * 16),
             (const char*)g_woutb + row * 1024 + c * 16);
    }
    CP_COMMIT();
    for (int i = t; i < 4096; i += 128) {
        int row = i >> 5, c = i & 31;
        cp16(smA0 + row * 512 + ((c ^ (row & 7)) * 16),
             (const char*)(g_hb + ((size_t)s * B_ + row) * H_) + c * 16);
    }
    CP_COMMIT();
    for (int i = t; i < 4096; i += 128) {
        int row = i >> 5, c = i & 31;
        cp16(smA1 + row * 512 + ((c ^ (row & 7)) * 16),
             (const char*)(g_hb + (size_t)S_ * B_ * H_ + ((size_t)s * B_ + row) * H_) + c * 16);
    }
    CP_COMMIT();

    const u32 smW_b = smem_u32(smW);

    float acc[2][8][4];
#pragma unroll
    for (int m = 0; m < 2; m++)
#pragma unroll
        for (int n = 0; n < 8; n++)
#pragma unroll
            for (int q = 0; q < 4; q++) acc[m][n][q] = 0.f;

    auto stage = [&](u32 smA_b, int wc0) {
#pragma unroll 4
        for (int kk = 0; kk < 16; kk++) {
            u32 a[2][4];
#pragma unroll
            for (int m = 0; m < 2; m++) {
                int row = w * 32 + m * 16 + (l & 15);
                int c = kk * 2 + (l >> 4);
                ldsm4(a[m][0], a[m][1], a[m][2], a[m][3],
                      smA_b + row * 512 + ((c ^ (row & 7)) * 16));
            }
#pragma unroll
            for (int nt = 0; nt < 8; nt++) {
                int row = nt * 8 + (l & 7);
                int c = wc0 + kk * 2 + ((l >> 3) & 1);
                u32 b0, b1;
                ldsm2(b0, b1, smW_b + row * 1024 + ((c ^ (row & 7)) * 16));
#pragma unroll
                for (int m = 0; m < 2; m++)
                    hmma(acc[m][nt], a[m][0], a[m][1], a[m][2], a[m][3], b0, b1);
            }
        }
    };

    CP_WAIT1();
    __syncthreads();
    stage(smem_u32(smA0), 0);
    CP_WAIT0();
    __syncthreads();
    stage(smem_u32(smA1), 32);

#pragma unroll
    for (int m = 0; m < 2; m++)
#pragma unroll
    for (int nt = 0; nt < 8; nt++) {
        int r  = w * 32 + m * 16 + (l >> 2);
        int jl = nt * 8 + 2 * (l & 3);
        if (jl < T_) {
            float b0 = bsm[jl], b1 = bsm[jl + 1];
            *(float2*)(g_emis + ((size_t)s * B_ + r) * T_ + jl)     = make_float2(acc[m][nt][0] + b0, acc[m][nt][1] + b1);
            *(float2*)(g_emis + ((size_t)s * B_ + r + 8) * T_ + jl) = make_float2(acc[m][nt][2] + b0, acc[m][nt][3] + b1);
        }
    }
}

// ---------------------------------------------------------------------------
// K4: CRF — one warp per batch element, 128 CTAs.
// ---------------------------------------------------------------------------
__global__ void __launch_bounds__(32) k_crf(
    const float* __restrict__ trans, const float* __restrict__ start_t,
    const float* __restrict__ end_t, const int* __restrict__ tags)
{
    __shared__ __align__(16) u64 Esp[T_ * 32];
    __shared__ float pw[64];

    const int b = blockIdx.x;
    const int l = threadIdx.x;

    for (int i = l; i < T_ * 32; i += 32) {
        int tt = i >> 5, c = i & 31;
        float e0 = expf(trans[tt * T_ + c]);
        float e1 = (c + 32 < T_) ? expf(trans[tt * T_ + c + 32]) : 0.f;
        Esp[i] = pk2(e0, e1);
    }
    __syncwarp();

    const bool v1 = (l + 32 < T_);
    float a0 = start_t[l] + g_emis[(size_t)b * T_ + l];
    float a1 = v1 ? (start_t[l + 32] + g_emis[(size_t)b * T_ + l + 32]) : -1e30f;

    float e0n = g_emis[((size_t)B_ + b) * T_ + l];
    float e1n = v1 ? g_emis[((size_t)B_ + b) * T_ + l + 32] : 0.f;

    for (int s = 1; s < S_; s++) {
        float e0 = e0n, e1 = e1n;
        if (s + 1 < S_) {
            const float* es = g_emis + ((size_t)(s + 1) * B_ + b) * T_;
            e0n = es[l];
            e1n = v1 ? es[l + 32] : 0.f;
        }

        float m = __shfl_sync(0xffffffffu, a0, 0);
        pw[l]      = __expf(a0 - m);
        pw[l + 32] = v1 ? __expf(a1 - m) : 0.f;
        __syncwarp();

        u64 q0 = 0ull, q1 = 0ull, q2 = 0ull, q3 = 0ull;
#pragma unroll
        for (int tt = 0; tt < 48; tt += 4) {
            q0 = f2ma(pk2(pw[tt],     pw[tt]),     Esp[(tt)     * 32 + l], q0);
            q1 = f2ma(pk2(pw[tt + 1], pw[tt + 1]), Esp[(tt + 1) * 32 + l], q1);
            q2 = f2ma(pk2(pw[tt + 2], pw[tt + 2]), Esp[(tt + 2) * 32 + l], q2);
            q3 = f2ma(pk2(pw[tt + 3], pw[tt + 3]), Esp[(tt + 3) * 32 + l], q3);
        }
        q0 = f2ma(pk2(pw[48], pw[48]), Esp[48 * 32 + l], q0);
        q1 = f2ma(pk2(pw[49], pw[49]), Esp[49 * 32 + l], q1);
        float2 qf = upk(f2add(f2add(q0, q1), f2add(q2, q3)));
        a0 = m + __logf(qf.x) + e0;
        a1 = v1 ? (m + __logf(qf.y) + e1) : -1e30f;
        __syncwarp();
    }

    float vv0 = a0 + end_t[l];
    float vv1 = v1 ? (a1 + end_t[l + 32]) : -1e30f;
    float m = fmaxf(vv0, vv1);
#pragma unroll
    for (int o = 16; o; o >>= 1) m = fmaxf(m, __shfl_xor_sync(0xffffffffu, m, o));
    float e = __expf(vv0 - m) + (v1 ? __expf(vv1 - m) : 0.f);
#pragma unroll
    for (int o = 16; o; o >>= 1) e += __shfl_xor_sync(0xffffffffu, e, o);
    float logZ = m + __logf(e);

    float acc = 0.f;
    for (int s = 1 + l; s < S_; s += 32) {
        int tp = tags[b * S_ + s - 1];
        int tc = tags[b * S_ + s];
        acc += trans[tp * T_ + tc] + g_emis[((size_t)s * B_ + b) * T_ + tc];
    }
#pragma unroll
    for (int o = 16; o; o >>= 1) acc += __shfl_xor_sync(0xffffffffu, acc, o);

    if (l == 0) {
        int t0 = tags[b * S_];
        int tl = tags[b * S_ + S_ - 1];
        g_res[b] = logZ - (start_t[t0] + g_emis[(size_t)b * T_ + t0] + acc + end_t[tl]);
    }
}

// ---------------------------------------------------------------------------
// K5: final mean
// ---------------------------------------------------------------------------
__global__ void k_final(float* __restrict__ out)
{
    __shared__ float red[4];
    int t = threadIdx.x;
    float v = g_res[t];
#pragma unroll
    for (int o = 16; o; o >>= 1) v += __shfl_xor_sync(0xffffffffu, v, o);
    if ((t & 31) == 0) red[t >> 5] = v;
    __syncthreads();
    if (t == 0) out[0] = (red[0] + red[1] + red[2] + red[3]) * (1.f / (float)B_);
}

// ---------------------------------------------------------------------------
// Launch
// ---------------------------------------------------------------------------
extern "C" void kernel_launch(void* const* d_in, const int* in_sizes, int n_in,
                              void* d_out, int out_size)
{
    const int*   sent  = (const int*)  d_in[0];
    const int*   tags  = (const int*)  d_in[1];
    const float* emb   = (const float*)d_in[3];
    const float* wih_f = (const float*)d_in[4];
    const float* whh_f = (const float*)d_in[5];
    const float* bih_f = (const float*)d_in[6];
    const float* bhh_f = (const float*)d_in[7];
    const float* wih_b = (const float*)d_in[8];
    const float* whh_b = (const float*)d_in[9];
    const float* bih_b = (const float*)d_in[10];
    const float* bhh_b = (const float*)d_in[11];
    const float* Wout  = (const float*)d_in[12];
    const float* bout  = (const float*)d_in[13];
    const float* strt  = (const float*)d_in[14];
    const float* endt  = (const float*)d_in[15];
    const float* trans = (const float*)d_in[16];
    float* out = (float*)d_out;

    const int input_smem = 199168;
    const int lstm_smem  = 50176;
    const int emis_smem  = 197888;
    cudaFuncSetAttribute(k_input, cudaFuncAttributeMaxDynamicSharedMemorySize, input_smem);
    cudaFuncSetAttribute(k_lstm,  cudaFuncAttributeMaxDynamicSharedMemorySize, lstm_smem);
    cudaFuncSetAttribute(k_emis,  cudaFuncAttributeMaxDynamicSharedMemorySize, emis_smem);

    int nconv = (EMB2 + 2 * WIH2 + WOUT2 + 255) / 256;
    k_convert<<<nconv, 256>>>(emb, wih_f, wih_b, Wout);
    k_input<<<dim3(8, 2, 256), 256, input_smem>>>(sent, bih_f, bhh_f, bih_b, bhh_b);
    k_lstm<<<128, 128, lstm_smem>>>(whh_f, whh_b);
    k_emis<<<512, 128, emis_smem>>>(bout);
    k_crf<<<128, 32>>>(trans, strt, endt, tags);
    k_final<<<1, 128>>>(out);
}